// round 4
// baseline (speedup 1.0000x reference)
#include <cuda_runtime.h>
#include <math.h>

#define N   2048
#define D   4096
#define NC  8
#define ROWSTRIDE (2 * D)     // features is (N, 2, D); anchor = features[:,0,:]

#define NBLK 512
#define NTHR 128
#define RA   (N / NBLK)       // 4 rows per block in phase A
#define CC   8                // column chunks in phase B (512 cols each)
#define RG   (NBLK / CC)      // 64 row groups
#define RB   (N / RG)         // 32 rows per group

// ---------------- device scratch (zero-init; counters self-reset each launch) ----
__device__ int    g_order[N];
__device__ int    g_cls[N];
__device__ int    g_counts[NC];
__device__ float  g_s[N];                    // per-row logsumexp
__device__ float  g_e[N];                    // per-row sum_k p*logp
__device__ __align__(16) float gA[NC * D];   // per-class column sums of p
__device__ __align__(16) float gX[NC * D];   // per-class column sums of x
__device__ double g_dot[NC + 1];
__device__ int    g_c1, g_c2, g_c3;

__device__ __forceinline__ void grid_sync(int* ctr) {
    __syncthreads();
    __threadfence();
    if (threadIdx.x == 0) {
        atomicAdd(ctr, 1);
        while (*((volatile int*)ctr) < NBLK) { }
    }
    __syncthreads();
    __threadfence();
}

__device__ __forceinline__ void flush4(int cls, int k0, float4 a, float4 xs) {
    float* pa = &gA[cls * D + k0];
    float* px = &gX[cls * D + k0];
    atomicAdd(pa + 0, a.x); atomicAdd(pa + 1, a.y);
    atomicAdd(pa + 2, a.z); atomicAdd(pa + 3, a.w);
    atomicAdd(px + 0, xs.x); atomicAdd(px + 1, xs.y);
    atomicAdd(px + 2, xs.z); atomicAdd(px + 3, xs.w);
}

__global__ void __launch_bounds__(NTHR, 4)
fused_all(const float* __restrict__ feat, const int* __restrict__ labels,
          float* __restrict__ out) {
    const int b = blockIdx.x;
    const int t = threadIdx.x;

    __shared__ float sred[4], sred2[4];
    __shared__ float sb1;
    __shared__ int   scnt[NC], soff[NC];

    // ================= PHASE A =================
    // zero slice of gA/gX : NBLK*NTHR == 2*NC*D exactly
    {
        int f = b * NTHR + t;
        if (f < NC * D) gA[f] = 0.f;
        else            gX[f - NC * D] = 0.f;
    }
    if (b == 0 && t < NC + 1) g_dot[t] = 0.0;

    // block 0: class-histogram + sort
    if (b == 0) {
        if (t < NC) scnt[t] = 0;
        __syncthreads();
        for (int i = t; i < N; i += NTHR) atomicAdd(&scnt[labels[i]], 1);
        __syncthreads();
        if (t == 0) {
            int run = 0;
            for (int c = 0; c < NC; c++) {
                soff[c] = run;
                g_counts[c] = scnt[c];
                run += scnt[c];
            }
        }
        __syncthreads();
        for (int i = t; i < N; i += NTHR) {
            int c = labels[i];
            int pos = atomicAdd(&soff[c], 1);
            g_order[pos] = i;
            g_cls[pos]   = c;
        }
    }

    // per-row logsumexp + entropy for this block's RA rows
    for (int r = 0; r < RA; r++) {
        const int i = b * RA + r;
        const float4* row = (const float4*)(feat + (long)i * ROWSTRIDE);
        float4 v[8];
        #pragma unroll
        for (int j = 0; j < 8; j++) v[j] = row[j * NTHR + t];

        float m = -INFINITY;
        #pragma unroll
        for (int j = 0; j < 8; j++)
            m = fmaxf(m, fmaxf(fmaxf(v[j].x, v[j].y), fmaxf(v[j].z, v[j].w)));
        #pragma unroll
        for (int o = 16; o; o >>= 1) m = fmaxf(m, __shfl_xor_sync(0xffffffffu, m, o));
        if ((t & 31) == 0) sred[t >> 5] = m;
        __syncthreads();
        if (t == 0) sb1 = fmaxf(fmaxf(sred[0], sred[1]), fmaxf(sred[2], sred[3]));
        __syncthreads();
        m = sb1;

        float z = 0.f, w = 0.f;
        #pragma unroll
        for (int j = 0; j < 8; j++) {
            float tx = v[j].x - m, ty = v[j].y - m, tz = v[j].z - m, tw = v[j].w - m;
            float qx = __expf(tx), qy = __expf(ty), qz = __expf(tz), qw = __expf(tw);
            z += qx + qy + qz + qw;
            w = fmaf(qx, tx, w); w = fmaf(qy, ty, w); w = fmaf(qz, tz, w); w = fmaf(qw, tw, w);
        }
        #pragma unroll
        for (int o = 16; o; o >>= 1) {
            z += __shfl_xor_sync(0xffffffffu, z, o);
            w += __shfl_xor_sync(0xffffffffu, w, o);
        }
        if ((t & 31) == 0) { sred[t >> 5] = z; sred2[t >> 5] = w; }
        __syncthreads();
        if (t == 0) {
            float Z = sred[0] + sred[1] + sred[2] + sred[3];
            float W = sred2[0] + sred2[1] + sred2[2] + sred2[3];
            float logZ = __logf(Z);
            g_s[i] = m + logZ;
            g_e[i] = W / Z - logZ;
        }
        __syncthreads();   // protect sred before next row reuse
    }

    grid_sync(&g_c1);

    // ================= PHASE B =================
    {
        const int cc = b % CC;
        const int rg = b / CC;
        __shared__ int   sfr[RB];
        __shared__ float ssv[RB];
        __shared__ int   scl[RB];
        if (t < RB) {
            int idx = rg * RB + t;
            int i = g_order[idx];
            sfr[t] = i * ROWSTRIDE;
            ssv[t] = g_s[i];
            scl[t] = g_cls[idx];
        }
        __syncthreads();

        const int k0 = cc * 512 + t * 4;
        float4 a  = make_float4(0.f, 0.f, 0.f, 0.f);
        float4 xs = make_float4(0.f, 0.f, 0.f, 0.f);
        int cur = scl[0];

        #pragma unroll 4
        for (int j = 0; j < RB; j++) {
            int cj = scl[j];
            if (cj != cur) {               // uniform across block (sorted rows)
                flush4(cur, k0, a, xs);
                a  = make_float4(0.f, 0.f, 0.f, 0.f);
                xs = make_float4(0.f, 0.f, 0.f, 0.f);
                cur = cj;
            }
            float4 x4 = *(const float4*)(feat + sfr[j] + k0);
            float sj = ssv[j];
            a.x += __expf(x4.x - sj); a.y += __expf(x4.y - sj);
            a.z += __expf(x4.z - sj); a.w += __expf(x4.w - sj);
            xs.x += x4.x; xs.y += x4.y; xs.z += x4.z; xs.w += x4.w;
        }
        flush4(cur, k0, a, xs);
    }

    grid_sync(&g_c2);

    // ================= PHASE C: dots (64 blocks x 64 cols) =================
    if (b < 64 && t < 64) {
        const int col = b * 64 + t;
        double part[NC + 1];
        float at = 0.f, xt = 0.f;
        #pragma unroll
        for (int c = 0; c < NC; c++) {
            float av = __ldcg(&gA[c * D + col]);
            float xv = __ldcg(&gX[c * D + col]);
            part[c] = (double)av * (double)xv;
            at += av;
            xt += xv;
        }
        part[NC] = (double)at * (double)xt;

        #pragma unroll
        for (int v = 0; v < NC + 1; v++) {
            double x = part[v];
            #pragma unroll
            for (int o = 16; o; o >>= 1) x += __shfl_xor_sync(0xffffffffu, x, o);
            if ((t & 31) == 0) atomicAdd(&g_dot[v], x);
        }
    }

    // ================= lights-out: last block finalizes =================
    __threadfence();
    __syncthreads();
    __shared__ int slast;
    if (t == 0) {
        int old = atomicAdd(&g_c3, 1);
        slast = (old == NBLK - 1) ? 1 : 0;
    }
    __syncthreads();
    if (!slast) return;
    __threadfence();

    __shared__ float sE[NC], sS[NC];
    if (t < NC) { sE[t] = 0.f; sS[t] = 0.f; }
    __syncthreads();
    for (int i = t; i < N; i += NTHR) {
        int c = labels[i];
        atomicAdd(&sE[c], __ldcg(&g_e[i]));
        atomicAdd(&sS[c], __ldcg(&g_s[i]));
    }
    __syncthreads();

    if (t == 0) {
        double same = 0.0, diff = 0.0, sumS = 0.0, Ss_tot = 0.0;
        for (int c = 0; c < NC; c++) {
            double n    = (double)g_counts[c];
            double Sc_s = (double)sS[c];
            double E    = (double)sE[c];
            double S    = __ldcg(&g_dot[c]) - Sc_s * n;     // dot(A_c, B_c)
            same += n * E - S;
            diff += ((double)N - n) * E;
            sumS += S;
            Ss_tot += Sc_s;
        }
        double Stot = __ldcg(&g_dot[NC]) - Ss_tot * (double)N;
        diff -= (Stot - sumS);
        out[0] = (float)(same / diff);

        // reset counters for the next graph replay (all blocks have passed all syncs)
        g_c1 = 0; g_c2 = 0; g_c3 = 0;
        __threadfence();
    }
}

extern "C" void kernel_launch(void* const* d_in, const int* in_sizes, int n_in,
                              void* d_out, int out_size) {
    const float* feat   = (const float*)d_in[0];
    const int*   labels = (const int*)d_in[1];
    float*       out    = (float*)d_out;
    (void)in_sizes; (void)n_in; (void)out_size;

    fused_all<<<NBLK, NTHR>>>(feat, labels, out);
}